// round 1
// baseline (speedup 1.0000x reference)
#include <cuda_runtime.h>
#include <math.h>

#define NN 20000
#define EE 200000
#define ND 64
#define ED 32
#define GD 32
#define HD 128
#define DOF 6
#define PI_F 3.14159265358979f

#define K1   172   // edge MLP input width
#define K1P  176   // padded to multiple of 8
#define FSTR 176   // smem stride of feature tile (16B aligned)
#define HSTR 132   // smem stride of hidden tile (16B aligned)
#define K3   224   // node MLP input width
#define GSTR 224

// scratch accumulators (no cudaMalloc allowed)
__device__ float g_sums[NN * HD];
__device__ float g_cnt[NN];

__global__ void zero_kernel() {
    int idx = blockIdx.x * blockDim.x + threadIdx.x;
    if (idx < NN * HD) g_sums[idx] = 0.0f;
    if (idx < NN)      g_cnt[idx]  = 0.0f;
}

// Tiled GEMM helper: S [64 x KTOT] (smem, stride sstride) @ Wg [KVALID x 128] (global)
// Thread layout: warp (0..7) owns rows warp*8..warp*8+7, lane owns cols lane*4..lane*4+3.
// acc[i][j] accumulates row (warp*8+i), col (lane*4+j).
template<int KTOT, int KVALID>
__device__ __forceinline__ void gemm_tile(const float* __restrict__ S, int sstride,
                                          const float* __restrict__ Wg,
                                          float* sW, int warp, int lane,
                                          float acc[8][4])
{
    const float* fbase = S + (warp * 8) * sstride;
    for (int kt = 0; kt < KTOT; kt += 8) {
        __syncthreads();
        for (int idx = (int)threadIdx.x; idx < 8 * HD; idx += 256) {
            int k = kt + (idx >> 7);
            sW[idx] = (k < KVALID) ? Wg[k * HD + (idx & 127)] : 0.0f;
        }
        __syncthreads();
        #pragma unroll
        for (int kk = 0; kk < 8; kk++) {
            float4 w = *(const float4*)(sW + kk * HD + lane * 4);
            #pragma unroll
            for (int i = 0; i < 8; i++) {
                float a = fbase[i * sstride + kt + kk];
                acc[i][0] += a * w.x;
                acc[i][1] += a * w.y;
                acc[i][2] += a * w.z;
                acc[i][3] += a * w.w;
            }
        }
    }
}

// ---------------- Edge kernel: 32 edges (64 feature rows) per block ----------------
__global__ __launch_bounds__(256, 2)
void edge_kernel(const float* __restrict__ xfeat, const float* __restrict__ T_R,
                 const float* __restrict__ T_t,  const float* __restrict__ edge_feat,
                 const float* __restrict__ TijR, const float* __restrict__ Tijt,
                 const int* __restrict__ ei,
                 const float* __restrict__ W1, const float* __restrict__ b1,
                 const float* __restrict__ W2, const float* __restrict__ b2)
{
    extern __shared__ float sm[];
    float* sF = sm;                  // 64 x FSTR
    float* sW = sF + 64 * FSTR;      // 8 x 128 staging
    float* sH = sW + 8 * HD;         // 64 x HSTR
    __shared__ int sNode[64];

    int tid = threadIdx.x;
    int e0 = blockIdx.x * 32;

    // ---- feature copy: xfeat_i, xfeat_j, edge_feat ----
    {
        int sub = tid & 7;
        int el  = tid >> 3;              // local edge 0..31
        int e   = e0 + el;
        int vi = ei[e], vj = ei[EE + e];
        const float4* xi4 = (const float4*)(xfeat + vi * ND);
        const float4* xj4 = (const float4*)(xfeat + vj * ND);
        const float4* ef4 = (const float4*)(edge_feat + e * ED);
        float* rowA = sF + el * FSTR;          // f_ij
        float* rowB = sF + (32 + el) * FSTR;   // f_ji
        #pragma unroll
        for (int q = sub; q < 16; q += 8) {
            float4 v = xi4[q];
            *(float4*)(rowA + q * 4)       = v;
            *(float4*)(rowB + 64 + q * 4)  = v;
            float4 w = xj4[q];
            *(float4*)(rowA + 64 + q * 4)  = w;
            *(float4*)(rowB + q * 4)       = w;
        }
        float4 v = ef4[sub];
        *(float4*)(rowA + 128 + sub * 4) = v;
        *(float4*)(rowB + 128 + sub * 4) = v;
    }

    // ---- relative pose features (1 thread per edge) ----
    if (tid < 32) {
        int e = e0 + tid;
        int vi = ei[e], vj = ei[EE + e];
        sNode[tid]      = vj;   // f_ij aggregates into j
        sNode[32 + tid] = vi;   // f_ji aggregates into i
        float Ri[9], Rj[9], Tr[9], ti[3], tj[3], tt[3];
        #pragma unroll
        for (int k = 0; k < 9; k++) { Ri[k] = T_R[vi*9+k]; Rj[k] = T_R[vj*9+k]; Tr[k] = TijR[e*9+k]; }
        #pragma unroll
        for (int k = 0; k < 3; k++) { ti[k] = T_t[vi*3+k]; tj[k] = T_t[vj*3+k]; tt[k] = Tijt[e*3+k]; }
        // A = Rj * Ri^T ; ta = tj - A ti
        float A[9], ta[3];
        #pragma unroll
        for (int r = 0; r < 3; r++)
            #pragma unroll
            for (int c = 0; c < 3; c++)
                A[r*3+c] = Rj[r*3+0]*Ri[c*3+0] + Rj[r*3+1]*Ri[c*3+1] + Rj[r*3+2]*Ri[c*3+2];
        #pragma unroll
        for (int r = 0; r < 3; r++)
            ta[r] = tj[r] - (A[r*3+0]*ti[0] + A[r*3+1]*ti[1] + A[r*3+2]*ti[2]);
        // Reij = A * Tr^T ; teij = ta - Reij * tt
        float Re[9], te[3];
        #pragma unroll
        for (int r = 0; r < 3; r++)
            #pragma unroll
            for (int c = 0; c < 3; c++)
                Re[r*3+c] = A[r*3+0]*Tr[c*3+0] + A[r*3+1]*Tr[c*3+1] + A[r*3+2]*Tr[c*3+2];
        #pragma unroll
        for (int r = 0; r < 3; r++)
            te[r] = ta[r] - (Re[r*3+0]*tt[0] + Re[r*3+1]*tt[1] + Re[r*3+2]*tt[2]);
        float* fA = sF + tid * FSTR + 160;
        fA[0]=Re[0]; fA[1]=Re[1]; fA[2]=Re[2];  fA[3]=te[0];
        fA[4]=Re[3]; fA[5]=Re[4]; fA[6]=Re[5];  fA[7]=te[1];
        fA[8]=Re[6]; fA[9]=Re[7]; fA[10]=Re[8]; fA[11]=te[2];
        fA[12]=0.f; fA[13]=0.f; fA[14]=0.f; fA[15]=0.f;
        // B = A^T ; tb = ti - B tj ; Reji = B * Tr ; teji = B tt + tb
        float tb[3], Rf[9], tf[3];
        #pragma unroll
        for (int r = 0; r < 3; r++)
            tb[r] = ti[r] - (A[0+r]*tj[0] + A[3+r]*tj[1] + A[6+r]*tj[2]);
        #pragma unroll
        for (int r = 0; r < 3; r++)
            #pragma unroll
            for (int c = 0; c < 3; c++)
                Rf[r*3+c] = A[0+r]*Tr[0+c] + A[3+r]*Tr[3+c] + A[6+r]*Tr[6+c];
        #pragma unroll
        for (int r = 0; r < 3; r++)
            tf[r] = tb[r] + (A[0+r]*tt[0] + A[3+r]*tt[1] + A[6+r]*tt[2]);
        float* fB = sF + (32 + tid) * FSTR + 160;
        fB[0]=Rf[0]; fB[1]=Rf[1]; fB[2]=Rf[2];  fB[3]=tf[0];
        fB[4]=Rf[3]; fB[5]=Rf[4]; fB[6]=Rf[5];  fB[7]=tf[1];
        fB[8]=Rf[6]; fB[9]=Rf[7]; fB[10]=Rf[8]; fB[11]=tf[2];
        fB[12]=0.f; fB[13]=0.f; fB[14]=0.f; fB[15]=0.f;
    }
    // (first gemm_tile chunk barrier orders the build)

    int warp = tid >> 5, lane = tid & 31;
    float acc[8][4];
    #pragma unroll
    for (int i = 0; i < 8; i++) { acc[i][0]=0.f; acc[i][1]=0.f; acc[i][2]=0.f; acc[i][3]=0.f; }
    gemm_tile<K1P, K1>(sF, FSTR, W1, sW, warp, lane, acc);

    float4 bv = *(const float4*)(b1 + lane * 4);
    #pragma unroll
    for (int i = 0; i < 8; i++) {
        float4 o;
        o.x = fmaxf(acc[i][0] + bv.x, 0.f);
        o.y = fmaxf(acc[i][1] + bv.y, 0.f);
        o.z = fmaxf(acc[i][2] + bv.z, 0.f);
        o.w = fmaxf(acc[i][3] + bv.w, 0.f);
        *(float4*)(sH + (warp * 8 + i) * HSTR + lane * 4) = o;
    }

    float acc2[8][4];
    #pragma unroll
    for (int i = 0; i < 8; i++) { acc2[i][0]=0.f; acc2[i][1]=0.f; acc2[i][2]=0.f; acc2[i][3]=0.f; }
    gemm_tile<HD, HD>(sH, HSTR, W2, sW, warp, lane, acc2);

    float4 b2v = *(const float4*)(b2 + lane * 4);
    #pragma unroll
    for (int i = 0; i < 8; i++) {
        int node = sNode[warp * 8 + i];
        float* dst = g_sums + node * HD + lane * 4;
        atomicAdd(dst + 0, fmaxf(acc2[i][0] + b2v.x, 0.f));
        atomicAdd(dst + 1, fmaxf(acc2[i][1] + b2v.y, 0.f));
        atomicAdd(dst + 2, fmaxf(acc2[i][2] + b2v.z, 0.f));
        atomicAdd(dst + 3, fmaxf(acc2[i][3] + b2v.w, 0.f));
    }
    if (tid < 64) atomicAdd(g_cnt + sNode[tid], 1.0f);
}

// ---------------- Node kernel: 64 nodes per block ----------------
__global__ __launch_bounds__(256, 1)
void node_kernel(const float* __restrict__ xfeat, const float* __restrict__ T_R,
                 const float* __restrict__ T_t,  const float* __restrict__ u,
                 const int* __restrict__ batch,
                 const float* __restrict__ W3, const float* __restrict__ b3,
                 const float* __restrict__ W4, const float* __restrict__ b4,
                 float* __restrict__ out)
{
    extern __shared__ float sm[];
    float* sG    = sm;                    // 64 x GSTR
    float* sW    = sG + 64 * GSTR;        // 8 x 128 staging
    float* sH    = sW + 8 * HD;           // 64 x HSTR
    float* sW4   = sH + 64 * HSTR;        // 128 x 70
    float* sPose = sW4 + HD * 70;         // 64 x 6

    int tid = threadIdx.x;
    int n0 = blockIdx.x * 64;

    // build g = [aggr(128) | xfeat(64) | u[batch](32)]
    for (int idx = tid; idx < 64 * HD; idx += 256) {
        int r = idx >> 7, c = idx & 127;
        int n = n0 + r;
        float v = 0.f;
        if (n < NN) v = g_sums[n * HD + c] / fmaxf(g_cnt[n], 1.0f);
        sG[r * GSTR + c] = v;
    }
    for (int idx = tid; idx < 64 * ND; idx += 256) {
        int r = idx >> 6, c = idx & 63;
        int n = n0 + r;
        sG[r * GSTR + HD + c] = (n < NN) ? xfeat[n * ND + c] : 0.f;
    }
    for (int idx = tid; idx < 64 * GD; idx += 256) {
        int r = idx >> 5, c = idx & 31;
        int n = n0 + r;
        sG[r * GSTR + HD + ND + c] = (n < NN) ? u[batch[n] * GD + c] : 0.f;
    }

    int warp = tid >> 5, lane = tid & 31;
    float acc[8][4];
    #pragma unroll
    for (int i = 0; i < 8; i++) { acc[i][0]=0.f; acc[i][1]=0.f; acc[i][2]=0.f; acc[i][3]=0.f; }
    gemm_tile<K3, K3>(sG, GSTR, W3, sW, warp, lane, acc);

    float4 bv = *(const float4*)(b3 + lane * 4);
    #pragma unroll
    for (int i = 0; i < 8; i++) {
        float4 o;
        o.x = fmaxf(acc[i][0] + bv.x, 0.f);
        o.y = fmaxf(acc[i][1] + bv.y, 0.f);
        o.z = fmaxf(acc[i][2] + bv.z, 0.f);
        o.w = fmaxf(acc[i][3] + bv.w, 0.f);
        *(float4*)(sH + (warp * 8 + i) * HSTR + lane * 4) = o;
    }
    __syncthreads();
    for (int idx = tid; idx < HD * 70; idx += 256) sW4[idx] = W4[idx];
    __syncthreads();

    // GEMM4: out cols = lane, 32+lane, 64+lane(lane<6)
    float a4[8][3];
    #pragma unroll
    for (int i = 0; i < 8; i++) { a4[i][0]=0.f; a4[i][1]=0.f; a4[i][2]=0.f; }
    const float* hb = sH + warp * 8 * HSTR;
    for (int k = 0; k < HD; k++) {
        float w0 = sW4[k * 70 + lane];
        float w1 = sW4[k * 70 + 32 + lane];
        float w2 = (lane < DOF) ? sW4[k * 70 + 64 + lane] : 0.f;
        #pragma unroll
        for (int i = 0; i < 8; i++) {
            float a = hb[i * HSTR + k];
            a4[i][0] += a * w0;
            a4[i][1] += a * w1;
            a4[i][2] += a * w2;
        }
    }
    float bb0 = b4[lane], bb1 = b4[32 + lane];
    float bb2 = (lane < DOF) ? b4[64 + lane] : 0.f;
    #pragma unroll
    for (int i = 0; i < 8; i++) {
        int r = warp * 8 + i;
        int n = n0 + r;
        if (n < NN) {
            out[(size_t)n * 77 + lane]      = xfeat[n * ND + lane]      + a4[i][0] + bb0;
            out[(size_t)n * 77 + 32 + lane] = xfeat[n * ND + 32 + lane] + a4[i][1] + bb1;
        }
        if (lane < DOF) sPose[r * DOF + lane] = a4[i][2] + bb2;
    }
    __syncthreads();

    // SE3 epilogue: one thread per node
    if (tid < 64) {
        int n = n0 + tid;
        if (n < NN) {
            float r0 = sPose[tid*6+0], r1 = sPose[tid*6+1], r2 = sPose[tid*6+2];
            float px = sPose[tid*6+3], py = sPose[tid*6+4], pz = sPose[tid*6+5];
            float nr = sqrtf(px*px + py*py + pz*pz);
            float sc = PI_F * tanhf(nr / PI_F) / (nr + 1e-8f);
            px *= sc; py *= sc; pz *= sc;
            float pp = px*px + py*py + pz*pz;
            float th = sqrtf(pp + 1e-12f);
            float a, b, c;
            if (th < 1e-4f) {
                a = 1.f - pp/6.f; b = 0.5f - pp/24.f; c = 1.f/6.f - pp/120.f;
            } else {
                float s = sinf(th), co = cosf(th);
                a = s / th; b = (1.f - co) / pp; c = (th - s) / (pp * th);
            }
            float Km[9] = {0.f,-pz,py,  pz,0.f,-px,  -py,px,0.f};
            float KK[9] = {px*px-pp, px*py,    px*pz,
                           py*px,    py*py-pp, py*pz,
                           pz*px,    pz*py,    pz*pz-pp};
            float Rd[9], V[9];
            #pragma unroll
            for (int q = 0; q < 9; q++) { Rd[q] = a*Km[q] + b*KK[q]; V[q] = b*Km[q] + c*KK[q]; }
            Rd[0] += 1.f; Rd[4] += 1.f; Rd[8] += 1.f;
            V[0]  += 1.f; V[4]  += 1.f; V[8]  += 1.f;
            float td0 = V[0]*r0 + V[1]*r1 + V[2]*r2;
            float td1 = V[3]*r0 + V[4]*r1 + V[5]*r2;
            float td2 = V[6]*r0 + V[7]*r1 + V[8]*r2;
            float TR[9], Tt[3];
            #pragma unroll
            for (int q = 0; q < 9; q++) TR[q] = T_R[n*9+q];
            #pragma unroll
            for (int q = 0; q < 3; q++) Tt[q] = T_t[n*3+q];
            float* o = out + (size_t)n * 77;
            #pragma unroll
            for (int rr = 0; rr < 3; rr++) {
                #pragma unroll
                for (int cc = 0; cc < 3; cc++) {
                    o[64 + rr*3 + cc] = Rd[rr*3+0]*TR[0+cc] + Rd[rr*3+1]*TR[3+cc] + Rd[rr*3+2]*TR[6+cc];
                }
                o[73 + rr] = Rd[rr*3+0]*Tt[0] + Rd[rr*3+1]*Tt[1] + Rd[rr*3+2]*Tt[2]
                           + (rr == 0 ? td0 : (rr == 1 ? td1 : td2));
            }
            o[76] = sqrtf(pp);
        }
    }
}

extern "C" void kernel_launch(void* const* d_in, const int* in_sizes, int n_in,
                              void* d_out, int out_size) {
    const float* xfeat     = (const float*)d_in[0];
    const float* T_R       = (const float*)d_in[1];
    const float* T_t       = (const float*)d_in[2];
    const float* edge_feat = (const float*)d_in[3];
    const float* TijR      = (const float*)d_in[4];
    const float* Tijt      = (const float*)d_in[5];
    const float* u         = (const float*)d_in[6];
    const int*   ei        = (const int*)d_in[7];
    const int*   batch     = (const int*)d_in[8];
    const float* W1 = (const float*)d_in[9];
    const float* b1 = (const float*)d_in[10];
    const float* W2 = (const float*)d_in[11];
    const float* b2 = (const float*)d_in[12];
    const float* W3 = (const float*)d_in[13];
    const float* b3 = (const float*)d_in[14];
    const float* W4 = (const float*)d_in[15];
    const float* b4 = (const float*)d_in[16];
    float* out = (float*)d_out;

    const int ESMEM = (64 * FSTR + 8 * HD + 64 * HSTR) * 4;               // 82944 B
    const int NSMEM = (64 * GSTR + 8 * HD + 64 * HSTR + HD * 70 + 64 * DOF) * 4; // 132608 B
    cudaFuncSetAttribute(edge_kernel, cudaFuncAttributeMaxDynamicSharedMemorySize, ESMEM);
    cudaFuncSetAttribute(node_kernel, cudaFuncAttributeMaxDynamicSharedMemorySize, NSMEM);

    zero_kernel<<<(NN * HD + 255) / 256, 256>>>();
    edge_kernel<<<EE / 32, 256, ESMEM>>>(xfeat, T_R, T_t, edge_feat, TijR, Tijt,
                                         ei, W1, b1, W2, b2);
    node_kernel<<<(NN + 63) / 64, 256, NSMEM>>>(xfeat, T_R, T_t, u, batch,
                                                W3, b3, W4, b4, out);
}